// round 1
// baseline (speedup 1.0000x reference)
#include <cuda_runtime.h>
#include <cuda_bf16.h>

#define HW     8192
#define THRESH 0.5f
#define RAD    4
#define TX     128     // output tile cols per block
#define TY     64      // output tile rows per block
#define IN_W   144     // loaded cols: TX + 16 (aligned halo: -8 .. +136)
#define IN_H   72      // loaded rows: TY + 8
#define NTHREADS 256

// smem layout: in_s[IN_H][IN_W], h_s[IN_H][TX]
#define SMEM_FLOATS (IN_H*IN_W + IN_H*TX)

__device__ __forceinline__ float4 f4max(float4 a, float4 b) {
    float4 r;
    r.x = fmaxf(a.x, b.x); r.y = fmaxf(a.y, b.y);
    r.z = fmaxf(a.z, b.z); r.w = fmaxf(a.w, b.w);
    return r;
}

__global__ void __launch_bounds__(NTHREADS, 2)
postprocess_kernel(const float* __restrict__ in, float* __restrict__ out)
{
    extern __shared__ float smem[];
    float* in_s = smem;                 // IN_H x IN_W
    float* h_s  = smem + IN_H * IN_W;   // IN_H x TX

    const int bx = blockIdx.x;          // 0..63
    const int by = blockIdx.y;          // 0..127
    const int tid = threadIdx.x;

    const int gr0 = by * TY - RAD;      // first loaded global row
    const int gc0 = bx * TX - 8;        // first loaded global col (16B aligned)

    // ---------------- Phase 1: load + threshold into smem ----------------
    // IN_H rows x (IN_W/4 = 36) float4s = 2592 vector loads
    for (int idx = tid; idx < IN_H * (IN_W / 4); idx += NTHREADS) {
        const int row  = idx / (IN_W / 4);
        const int col4 = (idx - row * (IN_W / 4)) * 4;
        const int gr = gr0 + row;
        const int gc = gc0 + col4;
        float4 v = make_float4(0.f, 0.f, 0.f, 0.f);
        if ((unsigned)gr < (unsigned)HW) {
            if (gc >= 0 && gc + 3 < HW) {
                v = *reinterpret_cast<const float4*>(&in[(size_t)gr * HW + gc]);
            } else {
                const float* rp = &in[(size_t)gr * HW];
                if ((unsigned)(gc + 0) < (unsigned)HW) v.x = rp[gc + 0];
                if ((unsigned)(gc + 1) < (unsigned)HW) v.y = rp[gc + 1];
                if ((unsigned)(gc + 2) < (unsigned)HW) v.z = rp[gc + 2];
                if ((unsigned)(gc + 3) < (unsigned)HW) v.w = rp[gc + 3];
            }
        }
        // threshold: keep strictly-above, else 0
        v.x = (v.x > THRESH) ? v.x : 0.f;
        v.y = (v.y > THRESH) ? v.y : 0.f;
        v.z = (v.z > THRESH) ? v.z : 0.f;
        v.w = (v.w > THRESH) ? v.w : 0.f;
        *reinterpret_cast<float4*>(&in_s[row * IN_W + col4]) = v;
    }
    __syncthreads();

    // ---------------- Phase 2: horizontal 9-max ----------------
    // For output col c (0..TX-1): window = in_s cols [c+4, c+12]
    // Process 4 outputs per thread-task using 3 float4 reads.
    for (int idx = tid; idx < IN_H * (TX / 4); idx += NTHREADS) {
        const int row = idx / (TX / 4);
        const int c   = (idx - row * (TX / 4)) * 4;
        const float* rp = &in_s[row * IN_W];
        const float4 a = *reinterpret_cast<const float4*>(&rp[c + 4]);
        const float4 b = *reinterpret_cast<const float4*>(&rp[c + 8]);
        const float4 d = *reinterpret_cast<const float4*>(&rp[c + 12]);
        // suffix maxes of a
        const float s3 = a.w;
        const float s2 = fmaxf(a.z, s3);
        const float s1 = fmaxf(a.y, s2);
        const float s0 = fmaxf(a.x, s1);
        // full max of b (shared by all four)
        const float mb = fmaxf(fmaxf(b.x, b.y), fmaxf(b.z, b.w));
        // prefix maxes of d
        const float p0 = d.x;
        const float p1 = fmaxf(p0, d.y);
        const float p2 = fmaxf(p1, d.z);
        const float p3 = fmaxf(p2, d.w);
        float4 o;
        o.x = fmaxf(fmaxf(s0, mb), p0);
        o.y = fmaxf(fmaxf(s1, mb), p1);
        o.z = fmaxf(fmaxf(s2, mb), p2);
        o.w = fmaxf(fmaxf(s3, mb), p3);
        *reinterpret_cast<float4*>(&h_s[row * TX + c]) = o;
    }
    __syncthreads();

    // ---------------- Phase 3: vertical 9-max + peak epilogue ----------------
    // 256 tasks: 32 col-groups (4 cols each) x 8 row-strips (8 rows each).
    {
        const int cg    = tid & 31;        // 0..31
        const int strip = tid >> 5;        // 0..7
        const int c  = cg * 4;
        const int r0 = strip * 8;

        // Load h_s rows r0 .. r0+15 (block A = first 8, block B = next 8)
        float4 hv[16];
#pragma unroll
        for (int j = 0; j < 16; j++)
            hv[j] = *reinterpret_cast<const float4*>(&h_s[(r0 + j) * TX + c]);

        // suffix maxes over block A in place: hv[i] = max(h[i..7])
#pragma unroll
        for (int i = 6; i >= 0; i--)
            hv[i] = f4max(hv[i], hv[i + 1]);

        float4 p = hv[8];  // running prefix max over block B
        const size_t gc = (size_t)(bx * TX + c);
#pragma unroll
        for (int r = 0; r < 8; r++) {
            if (r > 0) p = f4max(p, hv[8 + r]);
            const float4 mp = f4max(hv[r], p);   // 9-tap vertical max
            const float4 ctr = *reinterpret_cast<const float4*>(
                &in_s[(r0 + r + RAD) * IN_W + (c + 8)]);
            float4 o;
            o.x = (mp.x > 0.f && mp.x == ctr.x) ? mp.x : 0.f;
            o.y = (mp.y > 0.f && mp.y == ctr.y) ? mp.y : 0.f;
            o.z = (mp.z > 0.f && mp.z == ctr.z) ? mp.z : 0.f;
            o.w = (mp.w > 0.f && mp.w == ctr.w) ? mp.w : 0.f;
            const size_t grow = (size_t)(by * TY + r0 + r);
            *reinterpret_cast<float4*>(&out[grow * HW + gc]) = o;
        }
    }
}

extern "C" void kernel_launch(void* const* d_in, const int* in_sizes, int n_in,
                              void* d_out, int out_size)
{
    const float* in = (const float*)d_in[0];
    float* out = (float*)d_out;

    static bool attr_set = false;
    if (!attr_set) {
        cudaFuncSetAttribute(postprocess_kernel,
                             cudaFuncAttributeMaxDynamicSharedMemorySize,
                             SMEM_FLOATS * (int)sizeof(float));
        attr_set = true;
    }

    dim3 grid(HW / TX, HW / TY);   // 64 x 128
    postprocess_kernel<<<grid, NTHREADS, SMEM_FLOATS * sizeof(float)>>>(in, out);
}

// round 2
// speedup vs baseline: 1.0282x; 1.0282x over previous
#include <cuda_runtime.h>
#include <cuda_bf16.h>

#define HW     8192
#define THRESH 0.5f
#define RAD    4
#define TX     128     // output tile cols per block
#define TY     64      // output tile rows per block
#define IN_W   144     // loaded cols: TX + 16 (aligned halo: -8 .. +136)
#define IN_H   72      // loaded rows: TY + 8
#define NTHREADS 256

// smem layout: in_s[IN_H][IN_W], h_s[IN_H][TX]
#define SMEM_FLOATS (IN_H*IN_W + IN_H*TX)

__device__ __forceinline__ float4 f4max(float4 a, float4 b) {
    float4 r;
    r.x = fmaxf(a.x, b.x); r.y = fmaxf(a.y, b.y);
    r.z = fmaxf(a.z, b.z); r.w = fmaxf(a.w, b.w);
    return r;
}

__global__ void __launch_bounds__(NTHREADS, 2)
postprocess_kernel(const float* __restrict__ in, float* __restrict__ out)
{
    extern __shared__ float smem[];
    float* in_s = smem;                 // IN_H x IN_W
    float* h_s  = smem + IN_H * IN_W;   // IN_H x TX

    const int bx = blockIdx.x;          // 0..63
    const int by = blockIdx.y;          // 0..127
    const int tid = threadIdx.x;

    const int gr0 = by * TY - RAD;      // first loaded global row
    const int gc0 = bx * TX - 8;        // first loaded global col (16B aligned)

    // ---------------- Phase 1: load + threshold into smem ----------------
    // IN_H rows x (IN_W/4 = 36) float4s = 2592 vector loads
    for (int idx = tid; idx < IN_H * (IN_W / 4); idx += NTHREADS) {
        const int row  = idx / (IN_W / 4);
        const int col4 = (idx - row * (IN_W / 4)) * 4;
        const int gr = gr0 + row;
        const int gc = gc0 + col4;
        float4 v = make_float4(0.f, 0.f, 0.f, 0.f);
        if ((unsigned)gr < (unsigned)HW) {
            if (gc >= 0 && gc + 3 < HW) {
                v = *reinterpret_cast<const float4*>(&in[(size_t)gr * HW + gc]);
            } else {
                const float* rp = &in[(size_t)gr * HW];
                if ((unsigned)(gc + 0) < (unsigned)HW) v.x = rp[gc + 0];
                if ((unsigned)(gc + 1) < (unsigned)HW) v.y = rp[gc + 1];
                if ((unsigned)(gc + 2) < (unsigned)HW) v.z = rp[gc + 2];
                if ((unsigned)(gc + 3) < (unsigned)HW) v.w = rp[gc + 3];
            }
        }
        // threshold: keep strictly-above, else 0
        v.x = (v.x > THRESH) ? v.x : 0.f;
        v.y = (v.y > THRESH) ? v.y : 0.f;
        v.z = (v.z > THRESH) ? v.z : 0.f;
        v.w = (v.w > THRESH) ? v.w : 0.f;
        *reinterpret_cast<float4*>(&in_s[row * IN_W + col4]) = v;
    }
    __syncthreads();

    // ---------------- Phase 2: horizontal 9-max ----------------
    // For output col c (0..TX-1): window = in_s cols [c+4, c+12]
    // Process 4 outputs per thread-task using 3 float4 reads.
    for (int idx = tid; idx < IN_H * (TX / 4); idx += NTHREADS) {
        const int row = idx / (TX / 4);
        const int c   = (idx - row * (TX / 4)) * 4;
        const float* rp = &in_s[row * IN_W];
        const float4 a = *reinterpret_cast<const float4*>(&rp[c + 4]);
        const float4 b = *reinterpret_cast<const float4*>(&rp[c + 8]);
        const float4 d = *reinterpret_cast<const float4*>(&rp[c + 12]);
        // suffix maxes of a
        const float s3 = a.w;
        const float s2 = fmaxf(a.z, s3);
        const float s1 = fmaxf(a.y, s2);
        const float s0 = fmaxf(a.x, s1);
        // full max of b (shared by all four)
        const float mb = fmaxf(fmaxf(b.x, b.y), fmaxf(b.z, b.w));
        // prefix maxes of d
        const float p0 = d.x;
        const float p1 = fmaxf(p0, d.y);
        const float p2 = fmaxf(p1, d.z);
        const float p3 = fmaxf(p2, d.w);
        float4 o;
        o.x = fmaxf(fmaxf(s0, mb), p0);
        o.y = fmaxf(fmaxf(s1, mb), p1);
        o.z = fmaxf(fmaxf(s2, mb), p2);
        o.w = fmaxf(fmaxf(s3, mb), p3);
        *reinterpret_cast<float4*>(&h_s[row * TX + c]) = o;
    }
    __syncthreads();

    // ---------------- Phase 3: vertical 9-max + peak epilogue ----------------
    // 256 tasks: 32 col-groups (4 cols each) x 8 row-strips (8 rows each).
    {
        const int cg    = tid & 31;        // 0..31
        const int strip = tid >> 5;        // 0..7
        const int c  = cg * 4;
        const int r0 = strip * 8;

        // Load h_s rows r0 .. r0+15 (block A = first 8, block B = next 8)
        float4 hv[16];
#pragma unroll
        for (int j = 0; j < 16; j++)
            hv[j] = *reinterpret_cast<const float4*>(&h_s[(r0 + j) * TX + c]);

        // suffix maxes over block A in place: hv[i] = max(h[i..7])
#pragma unroll
        for (int i = 6; i >= 0; i--)
            hv[i] = f4max(hv[i], hv[i + 1]);

        float4 p = hv[8];  // running prefix max over block B
        const size_t gc = (size_t)(bx * TX + c);
#pragma unroll
        for (int r = 0; r < 8; r++) {
            if (r > 0) p = f4max(p, hv[8 + r]);
            const float4 mp = f4max(hv[r], p);   // 9-tap vertical max
            const float4 ctr = *reinterpret_cast<const float4*>(
                &in_s[(r0 + r + RAD) * IN_W + (c + 8)]);
            float4 o;
            o.x = (mp.x > 0.f && mp.x == ctr.x) ? mp.x : 0.f;
            o.y = (mp.y > 0.f && mp.y == ctr.y) ? mp.y : 0.f;
            o.z = (mp.z > 0.f && mp.z == ctr.z) ? mp.z : 0.f;
            o.w = (mp.w > 0.f && mp.w == ctr.w) ? mp.w : 0.f;
            const size_t grow = (size_t)(by * TY + r0 + r);
            *reinterpret_cast<float4*>(&out[grow * HW + gc]) = o;
        }
    }
}

extern "C" void kernel_launch(void* const* d_in, const int* in_sizes, int n_in,
                              void* d_out, int out_size)
{
    const float* in = (const float*)d_in[0];
    float* out = (float*)d_out;

    static bool attr_set = false;
    if (!attr_set) {
        cudaFuncSetAttribute(postprocess_kernel,
                             cudaFuncAttributeMaxDynamicSharedMemorySize,
                             SMEM_FLOATS * (int)sizeof(float));
        attr_set = true;
    }

    dim3 grid(HW / TX, HW / TY);   // 64 x 128
    postprocess_kernel<<<grid, NTHREADS, SMEM_FLOATS * sizeof(float)>>>(in, out);
}

// round 3
// speedup vs baseline: 1.0291x; 1.0009x over previous
#include <cuda_runtime.h>
#include <cuda_bf16.h>

#define HW     8192
#define THRESH 0.5f
#define RAD    4
#define TX     128     // output tile cols per block
#define TY     64      // output tile rows per block
#define IN_W   144     // loaded cols: TX + 16 (aligned halo: -8 .. +136)
#define IN_H   72      // loaded rows: TY + 8
#define NTHREADS 256

// smem layout: in_s[IN_H][IN_W], h_s[IN_H][TX]
#define SMEM_FLOATS (IN_H*IN_W + IN_H*TX)

__device__ __forceinline__ float4 f4max(float4 a, float4 b) {
    float4 r;
    r.x = fmaxf(a.x, b.x); r.y = fmaxf(a.y, b.y);
    r.z = fmaxf(a.z, b.z); r.w = fmaxf(a.w, b.w);
    return r;
}

__global__ void __launch_bounds__(NTHREADS, 2)
postprocess_kernel(const float* __restrict__ in, float* __restrict__ out)
{
    extern __shared__ float smem[];
    float* in_s = smem;                 // IN_H x IN_W
    float* h_s  = smem + IN_H * IN_W;   // IN_H x TX

    const int bx = blockIdx.x;          // 0..63
    const int by = blockIdx.y;          // 0..127
    const int tid = threadIdx.x;

    const int gr0 = by * TY - RAD;      // first loaded global row
    const int gc0 = bx * TX - 8;        // first loaded global col (16B aligned)

    // ---------------- Phase 1: load + threshold into smem ----------------
    // IN_H rows x (IN_W/4 = 36) float4s = 2592 vector loads
    for (int idx = tid; idx < IN_H * (IN_W / 4); idx += NTHREADS) {
        const int row  = idx / (IN_W / 4);
        const int col4 = (idx - row * (IN_W / 4)) * 4;
        const int gr = gr0 + row;
        const int gc = gc0 + col4;
        float4 v = make_float4(0.f, 0.f, 0.f, 0.f);
        if ((unsigned)gr < (unsigned)HW) {
            if (gc >= 0 && gc + 3 < HW) {
                v = *reinterpret_cast<const float4*>(&in[(size_t)gr * HW + gc]);
            } else {
                const float* rp = &in[(size_t)gr * HW];
                if ((unsigned)(gc + 0) < (unsigned)HW) v.x = rp[gc + 0];
                if ((unsigned)(gc + 1) < (unsigned)HW) v.y = rp[gc + 1];
                if ((unsigned)(gc + 2) < (unsigned)HW) v.z = rp[gc + 2];
                if ((unsigned)(gc + 3) < (unsigned)HW) v.w = rp[gc + 3];
            }
        }
        // threshold: keep strictly-above, else 0
        v.x = (v.x > THRESH) ? v.x : 0.f;
        v.y = (v.y > THRESH) ? v.y : 0.f;
        v.z = (v.z > THRESH) ? v.z : 0.f;
        v.w = (v.w > THRESH) ? v.w : 0.f;
        *reinterpret_cast<float4*>(&in_s[row * IN_W + col4]) = v;
    }
    __syncthreads();

    // ---------------- Phase 2: horizontal 9-max ----------------
    // For output col c (0..TX-1): window = in_s cols [c+4, c+12]
    // Process 4 outputs per thread-task using 3 float4 reads.
    for (int idx = tid; idx < IN_H * (TX / 4); idx += NTHREADS) {
        const int row = idx / (TX / 4);
        const int c   = (idx - row * (TX / 4)) * 4;
        const float* rp = &in_s[row * IN_W];
        const float4 a = *reinterpret_cast<const float4*>(&rp[c + 4]);
        const float4 b = *reinterpret_cast<const float4*>(&rp[c + 8]);
        const float4 d = *reinterpret_cast<const float4*>(&rp[c + 12]);
        // suffix maxes of a
        const float s3 = a.w;
        const float s2 = fmaxf(a.z, s3);
        const float s1 = fmaxf(a.y, s2);
        const float s0 = fmaxf(a.x, s1);
        // full max of b (shared by all four)
        const float mb = fmaxf(fmaxf(b.x, b.y), fmaxf(b.z, b.w));
        // prefix maxes of d
        const float p0 = d.x;
        const float p1 = fmaxf(p0, d.y);
        const float p2 = fmaxf(p1, d.z);
        const float p3 = fmaxf(p2, d.w);
        float4 o;
        o.x = fmaxf(fmaxf(s0, mb), p0);
        o.y = fmaxf(fmaxf(s1, mb), p1);
        o.z = fmaxf(fmaxf(s2, mb), p2);
        o.w = fmaxf(fmaxf(s3, mb), p3);
        *reinterpret_cast<float4*>(&h_s[row * TX + c]) = o;
    }
    __syncthreads();

    // ---------------- Phase 3: vertical 9-max + peak epilogue ----------------
    // 256 tasks: 32 col-groups (4 cols each) x 8 row-strips (8 rows each).
    {
        const int cg    = tid & 31;        // 0..31
        const int strip = tid >> 5;        // 0..7
        const int c  = cg * 4;
        const int r0 = strip * 8;

        // Load h_s rows r0 .. r0+15 (block A = first 8, block B = next 8)
        float4 hv[16];
#pragma unroll
        for (int j = 0; j < 16; j++)
            hv[j] = *reinterpret_cast<const float4*>(&h_s[(r0 + j) * TX + c]);

        // suffix maxes over block A in place: hv[i] = max(h[i..7])
#pragma unroll
        for (int i = 6; i >= 0; i--)
            hv[i] = f4max(hv[i], hv[i + 1]);

        float4 p = hv[8];  // running prefix max over block B
        const size_t gc = (size_t)(bx * TX + c);
#pragma unroll
        for (int r = 0; r < 8; r++) {
            if (r > 0) p = f4max(p, hv[8 + r]);
            const float4 mp = f4max(hv[r], p);   // 9-tap vertical max
            const float4 ctr = *reinterpret_cast<const float4*>(
                &in_s[(r0 + r + RAD) * IN_W + (c + 8)]);
            float4 o;
            o.x = (mp.x > 0.f && mp.x == ctr.x) ? mp.x : 0.f;
            o.y = (mp.y > 0.f && mp.y == ctr.y) ? mp.y : 0.f;
            o.z = (mp.z > 0.f && mp.z == ctr.z) ? mp.z : 0.f;
            o.w = (mp.w > 0.f && mp.w == ctr.w) ? mp.w : 0.f;
            const size_t grow = (size_t)(by * TY + r0 + r);
            *reinterpret_cast<float4*>(&out[grow * HW + gc]) = o;
        }
    }
}

extern "C" void kernel_launch(void* const* d_in, const int* in_sizes, int n_in,
                              void* d_out, int out_size)
{
    const float* in = (const float*)d_in[0];
    float* out = (float*)d_out;

    static bool attr_set = false;
    if (!attr_set) {
        cudaFuncSetAttribute(postprocess_kernel,
                             cudaFuncAttributeMaxDynamicSharedMemorySize,
                             SMEM_FLOATS * (int)sizeof(float));
        attr_set = true;
    }

    dim3 grid(HW / TX, HW / TY);   // 64 x 128
    postprocess_kernel<<<grid, NTHREADS, SMEM_FLOATS * sizeof(float)>>>(in, out);
}